// round 1
// baseline (speedup 1.0000x reference)
#include <cuda_runtime.h>

// Shapes are fixed by the problem definition.
#define BB    2
#define LL    2048
#define DD    1024
#define HH    16
#define HDIM  64
#define MR    (BB*LL)       // 4096 rows (B*L)
#define QKVN  (3*DD)        // 3072
#define NCH   (LL/64)       // 32 chunks of 64
#define SCALE 0.125f        // 1/sqrt(64)
#define TP    68            // padded stride for transposed smem tiles

// Scratch (device globals; no allocation allowed in kernel_launch)
__device__ float g_qkv[(size_t)MR * QKVN];                 // 50.3 MB
__device__ float g_u[(size_t)BB * HH * NCH * HDIM * HDIM]; // 16.8 MB
__device__ float g_y[(size_t)MR * DD];                     // 16.8 MB

// ---------------------------------------------------------------------------
// SGEMM (NT): C[M,N] = A[M,K] @ B[N,K]^T + bias[N]
// 128x128 tile, BK=16, 256 threads, 8x8 per-thread register tile.
// ---------------------------------------------------------------------------
__global__ __launch_bounds__(256, 2)
void sgemm_nt_bias(const float* __restrict__ A, const float* __restrict__ Bm,
                   const float* __restrict__ bias, float* __restrict__ C,
                   int M, int N, int K)
{
    __shared__ float As[16][132];
    __shared__ float Bs[16][132];

    const int tid = threadIdx.x;
    const int tx = tid & 15;
    const int ty = tid >> 4;
    const int rowBase = blockIdx.y * 128;
    const int colBase = blockIdx.x * 128;

    const int ldRow = tid >> 2;        // 0..63
    const int ldCol = (tid & 3) << 2;  // 0,4,8,12

    const float* Ap = A + (size_t)(rowBase + ldRow) * K + ldCol;
    const float* Bp = Bm + (size_t)(colBase + ldRow) * K + ldCol;

    float acc[8][8] = {};

    for (int k0 = 0; k0 < K; k0 += 16) {
        #pragma unroll
        for (int r = 0; r < 2; r++) {
            float4 va = *reinterpret_cast<const float4*>(Ap + (size_t)(r * 64) * K + k0);
            As[ldCol + 0][ldRow + r * 64] = va.x;
            As[ldCol + 1][ldRow + r * 64] = va.y;
            As[ldCol + 2][ldRow + r * 64] = va.z;
            As[ldCol + 3][ldRow + r * 64] = va.w;
            float4 vb = *reinterpret_cast<const float4*>(Bp + (size_t)(r * 64) * K + k0);
            Bs[ldCol + 0][ldRow + r * 64] = vb.x;
            Bs[ldCol + 1][ldRow + r * 64] = vb.y;
            Bs[ldCol + 2][ldRow + r * 64] = vb.z;
            Bs[ldCol + 3][ldRow + r * 64] = vb.w;
        }
        __syncthreads();
        #pragma unroll
        for (int k = 0; k < 16; k++) {
            float4 a0 = *reinterpret_cast<const float4*>(&As[k][ty * 8]);
            float4 a1 = *reinterpret_cast<const float4*>(&As[k][ty * 8 + 4]);
            float4 b0 = *reinterpret_cast<const float4*>(&Bs[k][tx * 8]);
            float4 b1 = *reinterpret_cast<const float4*>(&Bs[k][tx * 8 + 4]);
            float ra[8] = {a0.x, a0.y, a0.z, a0.w, a1.x, a1.y, a1.z, a1.w};
            float rb[8] = {b0.x, b0.y, b0.z, b0.w, b1.x, b1.y, b1.z, b1.w};
            #pragma unroll
            for (int i = 0; i < 8; i++)
                #pragma unroll
                for (int j = 0; j < 8; j++)
                    acc[i][j] += ra[i] * rb[j];
        }
        __syncthreads();
    }

    float bv[8];
    #pragma unroll
    for (int j = 0; j < 8; j++) bv[j] = bias[colBase + tx * 8 + j];

    #pragma unroll
    for (int i = 0; i < 8; i++) {
        float* Cp = C + (size_t)(rowBase + ty * 8 + i) * N + colBase + tx * 8;
        float4 o0 = make_float4(acc[i][0] + bv[0], acc[i][1] + bv[1],
                                acc[i][2] + bv[2], acc[i][3] + bv[3]);
        float4 o1 = make_float4(acc[i][4] + bv[4], acc[i][5] + bv[5],
                                acc[i][6] + bv[6], acc[i][7] + bv[7]);
        *reinterpret_cast<float4*>(Cp)     = o0;
        *reinterpret_cast<float4*>(Cp + 4) = o1;
    }
}

// ---------------------------------------------------------------------------
// Pass A: per-chunk U = (scale*K_c)^T @ V_c   [64x64 per (b,h,chunk)]
// ---------------------------------------------------------------------------
__global__ __launch_bounds__(256)
void chunk_kv_kernel(const float* __restrict__ qkv, float* __restrict__ U)
{
    __shared__ float Ks[64][64];  // [i][p]
    __shared__ float Vs[64][64];  // [i][q]

    const int idx = blockIdx.x;           // ((b*H)+h)*NCH + c
    const int c   = idx & (NCH - 1);
    const int bh  = idx >> 5;
    const int h   = bh & (HH - 1);
    const int b   = bh >> 4;

    const float* kb = qkv + ((size_t)(b * LL + c * 64)) * QKVN + DD + h * 64;
    const float* vb = kb + DD;
    const int tid = threadIdx.x;

    #pragma unroll
    for (int it = 0; it < 4; it++) {
        int e = tid + it * 256;
        int i = e >> 4;
        int c4 = (e & 15) << 2;
        float4 kv = *reinterpret_cast<const float4*>(kb + (size_t)i * QKVN + c4);
        Ks[i][c4 + 0] = kv.x * SCALE;
        Ks[i][c4 + 1] = kv.y * SCALE;
        Ks[i][c4 + 2] = kv.z * SCALE;
        Ks[i][c4 + 3] = kv.w * SCALE;
        float4 vv = *reinterpret_cast<const float4*>(vb + (size_t)i * QKVN + c4);
        *reinterpret_cast<float4*>(&Vs[i][c4]) = vv;
    }
    __syncthreads();

    const int tx = tid & 15;
    const int ty = tid >> 4;
    float acc[4][4] = {};
    #pragma unroll 8
    for (int i = 0; i < 64; i++) {
        float4 kp = *reinterpret_cast<const float4*>(&Ks[i][ty << 2]);
        float4 vq = *reinterpret_cast<const float4*>(&Vs[i][tx << 2]);
        float rk[4] = {kp.x, kp.y, kp.z, kp.w};
        float rv[4] = {vq.x, vq.y, vq.z, vq.w};
        #pragma unroll
        for (int p = 0; p < 4; p++)
            #pragma unroll
            for (int q = 0; q < 4; q++)
                acc[p][q] += rk[p] * rv[q];
    }

    float* ub = U + (size_t)idx * 4096;
    #pragma unroll
    for (int p = 0; p < 4; p++) {
        float4 o = make_float4(acc[p][0], acc[p][1], acc[p][2], acc[p][3]);
        *reinterpret_cast<float4*>(ub + (size_t)(((ty << 2) + p) * 64 + (tx << 2))) = o;
    }
}

// ---------------------------------------------------------------------------
// Pass B: in-place exclusive prefix over chunks of the 64x64 state per (b,h)
// ---------------------------------------------------------------------------
__global__ __launch_bounds__(256)
void scan_kernel(float* __restrict__ U)
{
    const int bh = blockIdx.x;     // 0..31
    const int tid = threadIdx.x;
    float* base = U + (size_t)bh * NCH * 4096;

    float4 run[4];
    #pragma unroll
    for (int g = 0; g < 4; g++) run[g] = make_float4(0.f, 0.f, 0.f, 0.f);

    for (int cix = 0; cix < NCH; cix++) {
        float4* p = reinterpret_cast<float4*>(base + (size_t)cix * 4096);
        #pragma unroll
        for (int g = 0; g < 4; g++) {
            float4 cur = p[tid + g * 256];
            p[tid + g * 256] = run[g];
            run[g].x += cur.x; run[g].y += cur.y;
            run[g].z += cur.z; run[g].w += cur.w;
        }
    }
}

// ---------------------------------------------------------------------------
// Pass C: Y_c = (Q_c (scale*K_c)^T ∘ tril) V_c + Q_c @ S_prefix
// One CTA per (b,h,chunk); 256 threads; dynamic smem ~83 KB.
// ---------------------------------------------------------------------------
__global__ __launch_bounds__(256)
void attn_out_kernel(const float* __restrict__ qkv, const float* __restrict__ S,
                     float* __restrict__ Y)
{
    extern __shared__ float sm[];
    float* QsT = sm;                  // [64][TP]  QsT[p][i] = q_i[p]
    float* KsT = QsT + 64 * TP;       // [64][TP]  KsT[p][j] = scale*k_j[p]
    float* AsT = KsT + 64 * TP;       // [64][TP]  AsT[j][i] = masked A[i][j]
    float* Vs  = AsT + 64 * TP;       // [64][64]
    float* Ss  = Vs + 64 * 64;        // [64][64]

    const int idx = blockIdx.x;
    const int c   = idx & (NCH - 1);
    const int bh  = idx >> 5;
    const int h   = bh & (HH - 1);
    const int b   = bh >> 4;

    const float* qb = qkv + ((size_t)(b * LL + c * 64)) * QKVN + h * 64;
    const float* kb = qb + DD;
    const float* vb = qb + 2 * DD;
    const float* sb = S + (size_t)idx * 4096;
    const int tid = threadIdx.x;

    // Transposed fills for Q, K
    {
        const int i = tid >> 2;                 // 0..63
        #pragma unroll
        for (int it = 0; it < 4; it++) {
            int c4 = ((tid & 3) + it * 4) << 2; // 0..60
            float4 q = *reinterpret_cast<const float4*>(qb + (size_t)i * QKVN + c4);
            QsT[(c4 + 0) * TP + i] = q.x;
            QsT[(c4 + 1) * TP + i] = q.y;
            QsT[(c4 + 2) * TP + i] = q.z;
            QsT[(c4 + 3) * TP + i] = q.w;
            float4 k = *reinterpret_cast<const float4*>(kb + (size_t)i * QKVN + c4);
            KsT[(c4 + 0) * TP + i] = k.x * SCALE;
            KsT[(c4 + 1) * TP + i] = k.y * SCALE;
            KsT[(c4 + 2) * TP + i] = k.z * SCALE;
            KsT[(c4 + 3) * TP + i] = k.w * SCALE;
        }
    }
    // Natural fills for V, S
    #pragma unroll
    for (int it = 0; it < 4; it++) {
        int e = tid + it * 256;
        int i = e >> 4;
        int c4 = (e & 15) << 2;
        float4 v = *reinterpret_cast<const float4*>(vb + (size_t)i * QKVN + c4);
        *reinterpret_cast<float4*>(&Vs[i * 64 + c4]) = v;
        float4 s = *reinterpret_cast<const float4*>(sb + (size_t)(i * 64 + c4));
        *reinterpret_cast<float4*>(&Ss[i * 64 + c4]) = s;
    }
    __syncthreads();

    const int tx = tid & 15;
    const int ty = tid >> 4;

    // Phase 1: AsT[j][i] = (j<=i) ? sum_p k_j[p]*q_i[p] : 0
    {
        float a[4][4] = {};
        #pragma unroll 4
        for (int p = 0; p < 64; p++) {
            float4 kj = *reinterpret_cast<const float4*>(&KsT[p * TP + (ty << 2)]);
            float4 qi = *reinterpret_cast<const float4*>(&QsT[p * TP + (tx << 2)]);
            float rk[4] = {kj.x, kj.y, kj.z, kj.w};
            float rq[4] = {qi.x, qi.y, qi.z, qi.w};
            #pragma unroll
            for (int jj = 0; jj < 4; jj++)
                #pragma unroll
                for (int ii = 0; ii < 4; ii++)
                    a[jj][ii] += rk[jj] * rq[ii];
        }
        #pragma unroll
        for (int jj = 0; jj < 4; jj++) {
            int j = (ty << 2) + jj;
            int i0 = tx << 2;
            float4 o;
            o.x = (j <= i0 + 0) ? a[jj][0] : 0.0f;
            o.y = (j <= i0 + 1) ? a[jj][1] : 0.0f;
            o.z = (j <= i0 + 2) ? a[jj][2] : 0.0f;
            o.w = (j <= i0 + 3) ? a[jj][3] : 0.0f;
            *reinterpret_cast<float4*>(&AsT[j * TP + i0]) = o;
        }
    }
    __syncthreads();

    // Phase 2: Y[i][dd] = sum_j A[i][j]*V[j][dd] + sum_p Q[i][p]*S[p][dd]
    {
        float acc[4][4] = {};
        #pragma unroll 4
        for (int j = 0; j < 64; j++) {
            float4 aj = *reinterpret_cast<const float4*>(&AsT[j * TP + (ty << 2)]);
            float4 vj = *reinterpret_cast<const float4*>(&Vs[j * 64 + (tx << 2)]);
            float ra[4] = {aj.x, aj.y, aj.z, aj.w};
            float rv[4] = {vj.x, vj.y, vj.z, vj.w};
            #pragma unroll
            for (int ii = 0; ii < 4; ii++)
                #pragma unroll
                for (int dd = 0; dd < 4; dd++)
                    acc[ii][dd] += ra[ii] * rv[dd];
        }
        #pragma unroll 4
        for (int p = 0; p < 64; p++) {
            float4 qp = *reinterpret_cast<const float4*>(&QsT[p * TP + (ty << 2)]);
            float4 sp = *reinterpret_cast<const float4*>(&Ss[p * 64 + (tx << 2)]);
            float rq[4] = {qp.x, qp.y, qp.z, qp.w};
            float rs[4] = {sp.x, sp.y, sp.z, sp.w};
            #pragma unroll
            for (int ii = 0; ii < 4; ii++)
                #pragma unroll
                for (int dd = 0; dd < 4; dd++)
                    acc[ii][dd] += rq[ii] * rs[dd];
        }
        float* yb = Y + ((size_t)(b * LL + c * 64)) * DD + h * 64;
        #pragma unroll
        for (int ii = 0; ii < 4; ii++) {
            float4 o = make_float4(acc[ii][0], acc[ii][1], acc[ii][2], acc[ii][3]);
            *reinterpret_cast<float4*>(yb + (size_t)((ty << 2) + ii) * DD + (tx << 2)) = o;
        }
    }
}

// ---------------------------------------------------------------------------
extern "C" void kernel_launch(void* const* d_in, const int* in_sizes, int n_in,
                              void* d_out, int out_size)
{
    const float* x      = (const float*)d_in[0];
    const float* Wqkv_w = (const float*)d_in[1];
    const float* Wqkv_b = (const float*)d_in[2];
    const float* out_w  = (const float*)d_in[3];
    const float* out_b  = (const float*)d_in[4];
    float* out = (float*)d_out;

    float *qkv, *u, *y;
    cudaGetSymbolAddress((void**)&qkv, g_qkv);
    cudaGetSymbolAddress((void**)&u,   g_u);
    cudaGetSymbolAddress((void**)&y,   g_y);

    const int smem_attn = (3 * 64 * TP + 2 * 64 * 64) * (int)sizeof(float); // 84992 B
    cudaFuncSetAttribute(attn_out_kernel,
                         cudaFuncAttributeMaxDynamicSharedMemorySize, smem_attn);

    // 1) QKV projection
    dim3 g1(QKVN / 128, MR / 128);  // 24 x 32
    sgemm_nt_bias<<<g1, 256>>>(x, Wqkv_w, Wqkv_b, qkv, MR, QKVN, DD);

    // 2) per-chunk K^T V
    chunk_kv_kernel<<<BB * HH * NCH, 256>>>(qkv, u);

    // 3) exclusive prefix over chunks (state scan)
    scan_kernel<<<BB * HH, 256>>>(u);

    // 4) intra-chunk causal attention + inter-chunk state contribution
    attn_out_kernel<<<BB * HH * NCH, 256, smem_attn>>>(qkv, u, y);

    // 5) output projection
    dim3 g2(DD / 128, MR / 128);    // 8 x 32
    sgemm_nt_bias<<<g2, 256>>>(y, out_w, out_b, out, MR, DD, DD);
}

// round 9
// speedup vs baseline: 1.9468x; 1.9468x over previous
#include <cuda_runtime.h>
#include <cuda_bf16.h>
#include <cstdint>

// ---------------------------------------------------------------------------
// Problem shapes (fixed)
// ---------------------------------------------------------------------------
#define BB    2
#define LL    2048
#define DD    1024
#define HH    16
#define MR    (BB*LL)       // 4096
#define QKVN  (3*DD)        // 3072
#define NCH   (LL/64)       // 32
#define SCALE 0.125f
#define TP    68

#define KP    3072          // split K' = 3*1024
#define NKIT  (KP/64)       // 48 K-iterations of 64 bf16

// ---------------------------------------------------------------------------
// Scratch (device globals)
// ---------------------------------------------------------------------------
__device__ float g_qkv[(size_t)MR * QKVN];
__device__ float g_u[(size_t)BB * HH * NCH * 64 * 64];
__device__ float g_y[(size_t)MR * DD];
__device__ __nv_bfloat16 g_a3[(size_t)MR * KP];     // split x (and later split y)
__device__ __nv_bfloat16 g_b3[(size_t)QKVN * KP];   // split Wqkv_w
__device__ __nv_bfloat16 g_w23[(size_t)DD * KP];    // split out_w

#define SW128(o) ((o) ^ (((o) >> 3) & 0x70))

__device__ __forceinline__ uint32_t smem_u32(const void* p) {
    uint32_t a;
    asm("{ .reg .u64 t; cvta.to.shared.u64 t, %1; cvt.u32.u64 %0, t; }" : "=r"(a) : "l"(p));
    return a;
}

// ---------------------------------------------------------------------------
// Split-precision conversion: fp32 -> 3x bf16 along K'
// ISB=0 (A-side): [hi | lo | hi]   ISB=1 (B-side): [hi | hi | lo]
// sum over K' = hi*hi + lo*hi + hi*lo  (drops only lo*lo ~ 2^-16 rel)
// ---------------------------------------------------------------------------
template <int ISB>
__global__ __launch_bounds__(256)
void split_convert(const float* __restrict__ src, __nv_bfloat16* __restrict__ dst, int total)
{
    int i = blockIdx.x * blockDim.x + threadIdx.x;
    if (i >= (total >> 1)) return;
    float2 v = reinterpret_cast<const float2*>(src)[i];
    int e = i << 1;
    int row = e >> 10;
    int col = e & 1023;
    __nv_bfloat16 h0 = __float2bfloat16(v.x);
    __nv_bfloat16 l0 = __float2bfloat16(v.x - __bfloat162float(h0));
    __nv_bfloat16 h1 = __float2bfloat16(v.y);
    __nv_bfloat16 l1 = __float2bfloat16(v.y - __bfloat162float(h1));
    size_t o = (size_t)row * KP + col;
    __nv_bfloat162 hh; hh.x = h0; hh.y = h1;
    __nv_bfloat162 ll; ll.x = l0; ll.y = l1;
    *reinterpret_cast<__nv_bfloat162*>(dst + o) = hh;
    if (ISB) {
        *reinterpret_cast<__nv_bfloat162*>(dst + o + 1024) = hh;
        *reinterpret_cast<__nv_bfloat162*>(dst + o + 2048) = ll;
    } else {
        *reinterpret_cast<__nv_bfloat162*>(dst + o + 1024) = ll;
        *reinterpret_cast<__nv_bfloat162*>(dst + o + 2048) = hh;
    }
}

// ---------------------------------------------------------------------------
// mma.sync bf16 NT GEMM: C[M,N] = A3[M,KP] @ B3[N,KP]^T + bias[N]
// CTA 128x128, BK=64, 8 warps (2m x 4n), warp tile 64x32, m16n8k16 HMMA.
// 4-stage cp.async pipeline, SW128-swizzled smem, ldmatrix fragment loads.
// ---------------------------------------------------------------------------
#define STAGES    4
#define GBM       128
#define GBN       128
#define A_ST      (GBM * 128)           // 16 KB
#define B_ST      (GBN * 128)           // 16 KB
#define ST_BYTES  (A_ST + B_ST)         // 32 KB
#define GEMM_SMEM (STAGES * ST_BYTES)   // 128 KB

__device__ __forceinline__ void ldsm_x4(uint32_t addr, uint32_t& r0, uint32_t& r1,
                                        uint32_t& r2, uint32_t& r3) {
    asm volatile("ldmatrix.sync.aligned.m8n8.x4.shared.b16 {%0,%1,%2,%3}, [%4];"
                 : "=r"(r0), "=r"(r1), "=r"(r2), "=r"(r3) : "r"(addr));
}
__device__ __forceinline__ void mma16816(float* c, const uint32_t* a, uint32_t b0, uint32_t b1) {
    asm volatile("mma.sync.aligned.m16n8k16.row.col.f32.bf16.bf16.f32 "
                 "{%0,%1,%2,%3}, {%4,%5,%6,%7}, {%8,%9}, {%0,%1,%2,%3};"
                 : "+f"(c[0]), "+f"(c[1]), "+f"(c[2]), "+f"(c[3])
                 : "r"(a[0]), "r"(a[1]), "r"(a[2]), "r"(a[3]), "r"(b0), "r"(b1));
}

__global__ __launch_bounds__(256, 1)
void gemm_mma_nt(const __nv_bfloat16* __restrict__ A, const __nv_bfloat16* __restrict__ Bm,
                 const float* __restrict__ bias, float* __restrict__ C, int N)
{
    extern __shared__ char smem[];
    const uint32_t sb = smem_u32(smem);
    const int tid  = threadIdx.x;
    const int wid  = tid >> 5;
    const int lane = tid & 31;
    const int wm   = wid & 1;    // 0..1  (64-row slab)
    const int wn   = wid >> 1;   // 0..3  (32-col slab)
    const int rowBase = blockIdx.y * GBM;
    const int colBase = blockIdx.x * GBN;

    const __nv_bfloat16* Ag = A + (size_t)rowBase * KP;
    const __nv_bfloat16* Bg = Bm + (size_t)colBase * KP;

    // Per-thread cp.async source/dest mapping: 8 x 16B per thread per stage
    const int ldr = tid >> 3;          // 0..31  (row group)
    const int ldc = tid & 7;           // 0..7   (16B chunk within 128B row)

    auto load_stage = [&](int stage, int k0) {
        uint32_t abase = sb + stage * ST_BYTES;
        uint32_t bbase = abase + A_ST;
        #pragma unroll
        for (int t = 0; t < 4; t++) {
            int r = ldr + t * 32;
            const __nv_bfloat16* g = Ag + (size_t)r * KP + k0 + ldc * 8;
            uint32_t s = abase + SW128((uint32_t)(r * 128 + ldc * 16));
            asm volatile("cp.async.cg.shared.global [%0], [%1], 16;" :: "r"(s), "l"(g));
        }
        #pragma unroll
        for (int t = 0; t < 4; t++) {
            int r = ldr + t * 32;
            const __nv_bfloat16* g = Bg + (size_t)r * KP + k0 + ldc * 8;
            uint32_t s = bbase + SW128((uint32_t)(r * 128 + ldc * 16));
            asm volatile("cp.async.cg.shared.global [%0], [%1], 16;" :: "r"(s), "l"(g));
        }
    };

    float acc[4][4][4];
    #pragma unroll
    for (int i = 0; i < 4; i++)
        #pragma unroll
        for (int j = 0; j < 4; j++)
            #pragma unroll
            for (int e = 0; e < 4; e++) acc[i][j][e] = 0.0f;

    // ldmatrix lane address components (byte offsets within the tile, pre-swizzle)
    // A: row = wm*64 + mi*16 + (lane&15), col16 = (lane>>4)
    const int aRow = wm * 64 + (lane & 15);
    const int aColB = (lane >> 4) * 16;
    // B: row = wn*32 + np*16 + (lane&7) + ((lane>>3)&1)*8, col16 = (lane>>4)
    const int bRow = wn * 32 + (lane & 7) + ((lane >> 3) & 1) * 8;
    const int bColB = (lane >> 4) * 16;

    #pragma unroll
    for (int s = 0; s < STAGES - 1; s++) {
        load_stage(s, s * 64);
        asm volatile("cp.async.commit_group;" ::: "memory");
    }

    for (int k = 0; k < NKIT; k++) {
        const int st = k & (STAGES - 1);
        asm volatile("cp.async.wait_group %0;" :: "n"(STAGES - 2) : "memory");
        __syncthreads();

        if (k + STAGES - 1 < NKIT)
            load_stage((k + STAGES - 1) & (STAGES - 1), (k + STAGES - 1) * 64);
        asm volatile("cp.async.commit_group;" ::: "memory");

        const uint32_t As = sb + st * ST_BYTES;
        const uint32_t Bs = As + A_ST;

        #pragma unroll
        for (int ks = 0; ks < 4; ks++) {
            uint32_t a[4][4];
            #pragma unroll
            for (int mi = 0; mi < 4; mi++) {
                uint32_t off = (uint32_t)((aRow + mi * 16) * 128 + ks * 32 + aColB);
                ldsm_x4(As + SW128(off), a[mi][0], a[mi][1], a[mi][2], a[mi][3]);
            }
            uint32_t b0[4], b1[4];
            #pragma unroll
            for (int np = 0; np < 2; np++) {
                uint32_t off = (uint32_t)((bRow + np * 16) * 128 + ks * 32 + bColB);
                ldsm_x4(Bs + SW128(off), b0[np * 2], b0[np * 2 + 1],
                        b1[np * 2], b1[np * 2 + 1]);
            }
            #pragma unroll
            for (int mi = 0; mi < 4; mi++)
                #pragma unroll
                for (int ni = 0; ni < 4; ni++)
                    mma16816(acc[mi][ni], a[mi], b0[ni], b1[ni]);
        }
    }

    // Epilogue: direct fp32 stores + bias
    const int erow = rowBase + wm * 64 + (lane >> 2);
    const int ecol = colBase + wn * 32 + (lane & 3) * 2;
    #pragma unroll
    for (int mi = 0; mi < 4; mi++) {
        #pragma unroll
        for (int ni = 0; ni < 4; ni++) {
            int r0 = erow + mi * 16;
            int c0 = ecol + ni * 8;
            float bx = bias[c0], by = bias[c0 + 1];
            float2 v0 = make_float2(acc[mi][ni][0] + bx, acc[mi][ni][1] + by);
            float2 v1 = make_float2(acc[mi][ni][2] + bx, acc[mi][ni][3] + by);
            *reinterpret_cast<float2*>(C + (size_t)r0 * N + c0)       = v0;
            *reinterpret_cast<float2*>(C + (size_t)(r0 + 8) * N + c0) = v1;
        }
    }
}

// ---------------------------------------------------------------------------
// Pass A: per-chunk U = (scale*K_c)^T @ V_c
// ---------------------------------------------------------------------------
__global__ __launch_bounds__(256)
void chunk_kv_kernel(const float* __restrict__ qkv, float* __restrict__ U)
{
    __shared__ float Ks[64][64];
    __shared__ float Vs[64][64];

    const int idx = blockIdx.x;
    const int c   = idx & (NCH - 1);
    const int bh  = idx >> 5;
    const int h   = bh & (HH - 1);
    const int b   = bh >> 4;

    const float* kb = qkv + ((size_t)(b * LL + c * 64)) * QKVN + DD + h * 64;
    const float* vb = kb + DD;
    const int tid = threadIdx.x;

    #pragma unroll
    for (int it = 0; it < 4; it++) {
        int e = tid + it * 256;
        int i = e >> 4;
        int c4 = (e & 15) << 2;
        float4 kv = *reinterpret_cast<const float4*>(kb + (size_t)i * QKVN + c4);
        Ks[i][c4 + 0] = kv.x * SCALE;
        Ks[i][c4 + 1] = kv.y * SCALE;
        Ks[i][c4 + 2] = kv.z * SCALE;
        Ks[i][c4 + 3] = kv.w * SCALE;
        float4 vv = *reinterpret_cast<const float4*>(vb + (size_t)i * QKVN + c4);
        *reinterpret_cast<float4*>(&Vs[i][c4]) = vv;
    }
    __syncthreads();

    const int tx = tid & 15;
    const int ty = tid >> 4;
    float acc[4][4] = {};
    #pragma unroll 8
    for (int i = 0; i < 64; i++) {
        float4 kp = *reinterpret_cast<const float4*>(&Ks[i][ty << 2]);
        float4 vq = *reinterpret_cast<const float4*>(&Vs[i][tx << 2]);
        float rk[4] = {kp.x, kp.y, kp.z, kp.w};
        float rv[4] = {vq.x, vq.y, vq.z, vq.w};
        #pragma unroll
        for (int p = 0; p < 4; p++)
            #pragma unroll
            for (int q = 0; q < 4; q++)
                acc[p][q] += rk[p] * rv[q];
    }

    float* ub = U + (size_t)idx * 4096;
    #pragma unroll
    for (int p = 0; p < 4; p++) {
        float4 o = make_float4(acc[p][0], acc[p][1], acc[p][2], acc[p][3]);
        *reinterpret_cast<float4*>(ub + (size_t)(((ty << 2) + p) * 64 + (tx << 2))) = o;
    }
}

// ---------------------------------------------------------------------------
// Pass B: exclusive chunk-prefix of 64x64 state per (b,h)
// ---------------------------------------------------------------------------
__global__ __launch_bounds__(256)
void scan_kernel(float* __restrict__ U)
{
    const int bh = blockIdx.x;
    const int tid = threadIdx.x;
    float* base = U + (size_t)bh * NCH * 4096;

    float4 run[4];
    #pragma unroll
    for (int g = 0; g < 4; g++) run[g] = make_float4(0.f, 0.f, 0.f, 0.f);

    for (int cix = 0; cix < NCH; cix++) {
        float4* p = reinterpret_cast<float4*>(base + (size_t)cix * 4096);
        #pragma unroll
        for (int g = 0; g < 4; g++) {
            float4 cur = p[tid + g * 256];
            p[tid + g * 256] = run[g];
            run[g].x += cur.x; run[g].y += cur.y;
            run[g].z += cur.z; run[g].w += cur.w;
        }
    }
}

// ---------------------------------------------------------------------------
// Pass C: Y_c = (Q_c (scale*K_c)^T ∘ tril) V_c + Q_c @ S_prefix
// ---------------------------------------------------------------------------
__global__ __launch_bounds__(256)
void attn_out_kernel(const float* __restrict__ qkv, const float* __restrict__ S,
                     float* __restrict__ Y)
{
    extern __shared__ float sm[];
    float* QsT = sm;
    float* KsT = QsT + 64 * TP;
    float* AsT = KsT + 64 * TP;
    float* Vs  = AsT + 64 * TP;
    float* Ss  = Vs + 64 * 64;

    const int idx = blockIdx.x;
    const int c   = idx & (NCH - 1);
    const int bh  = idx >> 5;
    const int h   = bh & (HH - 1);
    const int b   = bh >> 4;

    const float* qb = qkv + ((size_t)(b * LL + c * 64)) * QKVN + h * 64;
    const float* kb = qb + DD;
    const float* vb = qb + 2 * DD;
    const float* sb = S + (size_t)idx * 4096;
    const int tid = threadIdx.x;

    {
        const int i = tid >> 2;
        #pragma unroll
        for (int it = 0; it < 4; it++) {
            int c4 = ((tid & 3) + it * 4) << 2;
            float4 q = *reinterpret_cast<const float4*>(qb + (size_t)i * QKVN + c4);
            QsT[(c4 + 0) * TP + i] = q.x;
            QsT[(c4 + 1) * TP + i] = q.y;
            QsT[(c4 + 2) * TP + i] = q.z;
            QsT[(c4 + 3) * TP + i] = q.w;
            float4 k = *reinterpret_cast<const float4*>(kb + (size_t)i * QKVN + c4);
            KsT[(c4 + 0) * TP + i] = k.x * SCALE;
            KsT[(c4 + 1) * TP + i] = k.y * SCALE;
            KsT[(c4 + 2) * TP + i] = k.z * SCALE;
            KsT[(c4 + 3) * TP + i] = k.w * SCALE;
        }
    }
    #pragma unroll
    for (int it = 0; it < 4; it++) {
        int e = tid + it * 256;
        int i = e >> 4;
        int c4 = (e & 15) << 2;
        float4 v = *reinterpret_cast<const float4*>(vb + (size_t)i * QKVN + c4);
        *reinterpret_cast<float4*>(&Vs[i * 64 + c4]) = v;
        float4 s = *reinterpret_cast<const float4*>(sb + (size_t)(i * 64 + c4));
        *reinterpret_cast<float4*>(&Ss[i * 64 + c4]) = s;
    }
    __syncthreads();

    const int tx = tid & 15;
    const int ty = tid >> 4;

    {
        float a[4][4] = {};
        #pragma unroll 4
        for (int p = 0; p < 64; p++) {
            float4 kj = *reinterpret_cast<const float4*>(&KsT[p * TP + (ty << 2)]);
            float4 qi = *reinterpret_cast<const float4*>(&QsT[p * TP + (tx << 2)]);
            float rk[4] = {kj.x, kj.y, kj.z, kj.w};
            float rq[4] = {qi.x, qi.y, qi.z, qi.w};
            #pragma unroll
            for (int jj = 0; jj < 4; jj++)
                #pragma unroll
                for (int ii = 0; ii < 4; ii++)
                    a[jj][ii] += rk[jj] * rq[ii];
        }
        #pragma unroll
        for (int jj = 0; jj < 4; jj++) {
            int j = (ty << 2) + jj;
            int i0 = tx << 2;
            float4 o;
            o.x = (j <= i0 + 0) ? a[jj][0] : 0.0f;
            o.y = (j <= i0 + 1) ? a[jj][1] : 0.0f;
            o.z = (j <= i0 + 2) ? a[jj][2] : 0.0f;
            o.w = (j <= i0 + 3) ? a[jj][3] : 0.0f;
            *reinterpret_cast<float4*>(&AsT[j * TP + i0]) = o;
        }
    }
    __syncthreads();

    {
        float acc[4][4] = {};
        #pragma unroll 4
        for (int j = 0; j < 64; j++) {
            float4 aj = *reinterpret_cast<const float4*>(&AsT[j * TP + (ty << 2)]);
            float4 vj = *reinterpret_cast<const float4*>(&Vs[j * 64 + (tx << 2)]);
            float ra[4] = {aj.x, aj.y, aj.z, aj.w};
            float rv[4] = {vj.x, vj.y, vj.z, vj.w};
            #pragma unroll
            for (int ii = 0; ii < 4; ii++)
                #pragma unroll
                for (int dd = 0; dd < 4; dd++)
                    acc[ii][dd] += ra[ii] * rv[dd];
        }
        #pragma unroll 4
        for (int p = 0; p < 64; p++) {
            float4 qp = *reinterpret_cast<const float4*>(&QsT[p * TP + (ty << 2)]);
            float4 sp = *reinterpret_cast<const float4*>(&Ss[p * 64 + (tx << 2)]);
            float rq[4] = {qp.x, qp.y, qp.z, qp.w};
            float rs[4] = {sp.x, sp.y, sp.z, sp.w};
            #pragma unroll
            for (int ii = 0; ii < 4; ii++)
                #pragma unroll
                for (int dd = 0; dd < 4; dd++)
                    acc[ii][dd] += rq[ii] * rs[dd];
        }
        float* yb = Y + ((size_t)(b * LL + c * 64)) * DD + h * 64;
        #pragma unroll
        for (int ii = 0; ii < 4; ii++) {
            float4 o = make_float4(acc[ii][0], acc[ii][1], acc[ii][2], acc[ii][3]);
            *reinterpret_cast<float4*>(yb + (size_t)((ty << 2) + ii) * DD + (tx << 2)) = o;
        }
    }
}

// ---------------------------------------------------------------------------
extern "C" void kernel_launch(void* const* d_in, const int* in_sizes, int n_in,
                              void* d_out, int out_size)
{
    const float* x      = (const float*)d_in[0];
    const float* Wqkv_w = (const float*)d_in[1];
    const float* Wqkv_b = (const float*)d_in[2];
    const float* out_w  = (const float*)d_in[3];
    const float* out_b  = (const float*)d_in[4];
    float* out = (float*)d_out;

    float *qkv, *u, *y;
    __nv_bfloat16 *a3, *b3, *w23;
    cudaGetSymbolAddress((void**)&qkv, g_qkv);
    cudaGetSymbolAddress((void**)&u,   g_u);
    cudaGetSymbolAddress((void**)&y,   g_y);
    cudaGetSymbolAddress((void**)&a3,  g_a3);
    cudaGetSymbolAddress((void**)&b3,  g_b3);
    cudaGetSymbolAddress((void**)&w23, g_w23);

    const int smem_attn = (3 * 64 * TP + 2 * 64 * 64) * (int)sizeof(float);
    cudaFuncSetAttribute(attn_out_kernel,
                         cudaFuncAttributeMaxDynamicSharedMemorySize, smem_attn);
    cudaFuncSetAttribute(gemm_mma_nt,
                         cudaFuncAttributeMaxDynamicSharedMemorySize, GEMM_SMEM);

    // 1) split conversions for QKV GEMM
    split_convert<0><<<(MR * DD / 2 + 255) / 256, 256>>>(x, a3, MR * DD);
    split_convert<1><<<(QKVN * DD / 2 + 255) / 256, 256>>>(Wqkv_w, b3, QKVN * DD);

    // 2) QKV projection on tensor cores (HMMA)
    dim3 g1(QKVN / GBN, MR / GBM);  // 24 x 32
    gemm_mma_nt<<<g1, 256, GEMM_SMEM>>>(a3, b3, Wqkv_b, qkv, QKVN);

    // 3) chunked linear attention (fp32)
    chunk_kv_kernel<<<BB * HH * NCH, 256>>>(qkv, u);
    scan_kernel<<<BB * HH, 256>>>(u);
    attn_out_kernel<<<BB * HH * NCH, 256, smem_attn>>>(qkv, u, y);

    // 4) split conversions for output GEMM (reuse a3 for y)
    split_convert<0><<<(MR * DD / 2 + 255) / 256, 256>>>(y, a3, MR * DD);
    split_convert<1><<<(DD * DD / 2 + 255) / 256, 256>>>(out_w, w23, DD * DD);

    // 5) output projection on tensor cores (HMMA)
    dim3 g2(DD / GBN, MR / GBM);    // 8 x 32
    gemm_mma_nt<<<g2, 256, GEMM_SMEM>>>(a3, w23, out_b, out, DD);
}

// round 12
// speedup vs baseline: 2.0932x; 1.0752x over previous
#include <cuda_runtime.h>
#include <cuda_bf16.h>
#include <cstdint>

// ---------------------------------------------------------------------------
// Problem shapes (fixed)
// ---------------------------------------------------------------------------
#define BB    2
#define LL    2048
#define DD    1024
#define HH    16
#define MR    (BB*LL)       // 4096
#define QKVN  (3*DD)        // 3072
#define NCH   (LL/64)       // 32
#define SCALE 0.125f
#define TP    68

#define KP    3072          // split K' = 3*1024
#define NKIT  (KP/64)       // 48 K-iterations of 64 bf16

// ---------------------------------------------------------------------------
// Scratch (device globals)
// ---------------------------------------------------------------------------
__device__ float g_qkv[(size_t)MR * QKVN];
__device__ float g_u[(size_t)BB * HH * NCH * 64 * 64];
__device__ __nv_bfloat16 g_a3[(size_t)MR * KP];     // split x (then split y, written by attn_out)
__device__ __nv_bfloat16 g_b3[(size_t)QKVN * KP];   // split Wqkv_w
__device__ __nv_bfloat16 g_w23[(size_t)DD * KP];    // split out_w

#define SW128(o) ((o) ^ (((o) >> 3) & 0x70))

__device__ __forceinline__ uint32_t smem_u32(const void* p) {
    uint32_t a;
    asm("{ .reg .u64 t; cvta.to.shared.u64 t, %1; cvt.u32.u64 %0, t; }" : "=r"(a) : "l"(p));
    return a;
}

// ---------------------------------------------------------------------------
// Split-precision conversion: fp32 -> 3x bf16 along K'
// ISB=0 (A-side): [hi | lo | hi]   ISB=1 (B-side): [hi | hi | lo]
// sum over K' = hi*hi + lo*hi + hi*lo  (drops only lo*lo ~ 2^-16 rel)
// ---------------------------------------------------------------------------
template <int ISB>
__global__ __launch_bounds__(256)
void split_convert(const float* __restrict__ src, __nv_bfloat16* __restrict__ dst, int total)
{
    int i = blockIdx.x * blockDim.x + threadIdx.x;
    if (i >= (total >> 1)) return;
    float2 v = reinterpret_cast<const float2*>(src)[i];
    int e = i << 1;
    int row = e >> 10;
    int col = e & 1023;
    __nv_bfloat16 h0 = __float2bfloat16(v.x);
    __nv_bfloat16 l0 = __float2bfloat16(v.x - __bfloat162float(h0));
    __nv_bfloat16 h1 = __float2bfloat16(v.y);
    __nv_bfloat16 l1 = __float2bfloat16(v.y - __bfloat162float(h1));
    size_t o = (size_t)row * KP + col;
    __nv_bfloat162 hh; hh.x = h0; hh.y = h1;
    __nv_bfloat162 ll; ll.x = l0; ll.y = l1;
    *reinterpret_cast<__nv_bfloat162*>(dst + o) = hh;
    if (ISB) {
        *reinterpret_cast<__nv_bfloat162*>(dst + o + 1024) = hh;
        *reinterpret_cast<__nv_bfloat162*>(dst + o + 2048) = ll;
    } else {
        *reinterpret_cast<__nv_bfloat162*>(dst + o + 1024) = ll;
        *reinterpret_cast<__nv_bfloat162*>(dst + o + 2048) = hh;
    }
}

// ---------------------------------------------------------------------------
// mma.sync bf16 NT GEMM: C[M,N] = A3[M,KP] @ B3[N,KP]^T + bias[N]
// CTA 128x256, BK=64, 8 warps (2m x 4n), warp tile 64x64, m16n8k16 HMMA.
// 4-stage cp.async pipeline, SW128-swizzled smem, ldmatrix fragment loads.
// ---------------------------------------------------------------------------
#define STAGES    4
#define GBM       128
#define GBN       256
#define A_ST      (GBM * 128)           // 16 KB
#define B_ST      (GBN * 128)           // 32 KB
#define ST_BYTES  (A_ST + B_ST)         // 48 KB
#define GEMM_SMEM (STAGES * ST_BYTES)   // 192 KB

__device__ __forceinline__ void ldsm_x4(uint32_t addr, uint32_t& r0, uint32_t& r1,
                                        uint32_t& r2, uint32_t& r3) {
    asm volatile("ldmatrix.sync.aligned.m8n8.x4.shared.b16 {%0,%1,%2,%3}, [%4];"
                 : "=r"(r0), "=r"(r1), "=r"(r2), "=r"(r3) : "r"(addr));
}
__device__ __forceinline__ void mma16816(float* c, const uint32_t* a, uint32_t b0, uint32_t b1) {
    asm volatile("mma.sync.aligned.m16n8k16.row.col.f32.bf16.bf16.f32 "
                 "{%0,%1,%2,%3}, {%4,%5,%6,%7}, {%8,%9}, {%0,%1,%2,%3};"
                 : "+f"(c[0]), "+f"(c[1]), "+f"(c[2]), "+f"(c[3])
                 : "r"(a[0]), "r"(a[1]), "r"(a[2]), "r"(a[3]), "r"(b0), "r"(b1));
}

__global__ __launch_bounds__(256, 1)
void gemm_mma_nt(const __nv_bfloat16* __restrict__ A, const __nv_bfloat16* __restrict__ Bm,
                 const float* __restrict__ bias, float* __restrict__ C, int N)
{
    extern __shared__ char smem[];
    const uint32_t sb = smem_u32(smem);
    const int tid  = threadIdx.x;
    const int wid  = tid >> 5;
    const int lane = tid & 31;
    const int wm   = wid & 1;    // 0..1  (64-row slab)
    const int wn   = wid >> 1;   // 0..3  (64-col slab)
    const int rowBase = blockIdx.y * GBM;
    const int colBase = blockIdx.x * GBN;

    const __nv_bfloat16* Ag = A + (size_t)rowBase * KP;
    const __nv_bfloat16* Bg = Bm + (size_t)colBase * KP;

    const int ldr = tid >> 3;          // 0..31  (row group)
    const int ldc = tid & 7;           // 0..7   (16B chunk within 128B row)

    auto load_stage = [&](int stage, int k0) {
        uint32_t abase = sb + stage * ST_BYTES;
        uint32_t bbase = abase + A_ST;
        #pragma unroll
        for (int t = 0; t < 4; t++) {
            int r = ldr + t * 32;
            const __nv_bfloat16* g = Ag + (size_t)r * KP + k0 + ldc * 8;
            uint32_t s = abase + SW128((uint32_t)(r * 128 + ldc * 16));
            asm volatile("cp.async.cg.shared.global [%0], [%1], 16;" :: "r"(s), "l"(g));
        }
        #pragma unroll
        for (int t = 0; t < 8; t++) {
            int r = ldr + t * 32;
            const __nv_bfloat16* g = Bg + (size_t)r * KP + k0 + ldc * 8;
            uint32_t s = bbase + SW128((uint32_t)(r * 128 + ldc * 16));
            asm volatile("cp.async.cg.shared.global [%0], [%1], 16;" :: "r"(s), "l"(g));
        }
    };

    float acc[4][8][4];
    #pragma unroll
    for (int i = 0; i < 4; i++)
        #pragma unroll
        for (int j = 0; j < 8; j++)
            #pragma unroll
            for (int e = 0; e < 4; e++) acc[i][j][e] = 0.0f;

    // A: row = wm*64 + mi*16 + (lane&15), col16 = (lane>>4)
    const int aRow = wm * 64 + (lane & 15);
    const int aColB = (lane >> 4) * 16;
    // B: row = wn*64 + np*16 + (lane&7) + ((lane>>3)&1)*8, col16 = (lane>>4)
    const int bRow = wn * 64 + (lane & 7) + ((lane >> 3) & 1) * 8;
    const int bColB = (lane >> 4) * 16;

    #pragma unroll
    for (int s = 0; s < STAGES - 1; s++) {
        load_stage(s, s * 64);
        asm volatile("cp.async.commit_group;" ::: "memory");
    }

    for (int k = 0; k < NKIT; k++) {
        const int st = k & (STAGES - 1);
        asm volatile("cp.async.wait_group %0;" :: "n"(STAGES - 2) : "memory");
        __syncthreads();

        if (k + STAGES - 1 < NKIT)
            load_stage((k + STAGES - 1) & (STAGES - 1), (k + STAGES - 1) * 64);
        asm volatile("cp.async.commit_group;" ::: "memory");

        const uint32_t As = sb + st * ST_BYTES;
        const uint32_t Bs = As + A_ST;

        #pragma unroll
        for (int ks = 0; ks < 4; ks++) {
            uint32_t a[4][4];
            #pragma unroll
            for (int mi = 0; mi < 4; mi++) {
                uint32_t off = (uint32_t)((aRow + mi * 16) * 128 + ks * 32 + aColB);
                ldsm_x4(As + SW128(off), a[mi][0], a[mi][1], a[mi][2], a[mi][3]);
            }
            uint32_t b0[8], b1[8];
            #pragma unroll
            for (int np = 0; np < 4; np++) {
                uint32_t off = (uint32_t)((bRow + np * 16) * 128 + ks * 32 + bColB);
                ldsm_x4(Bs + SW128(off), b0[np * 2], b0[np * 2 + 1],
                        b1[np * 2], b1[np * 2 + 1]);
            }
            #pragma unroll
            for (int mi = 0; mi < 4; mi++)
                #pragma unroll
                for (int ni = 0; ni < 8; ni++)
                    mma16816(acc[mi][ni], a[mi], b0[ni], b1[ni]);
        }
    }

    // Epilogue: direct fp32 stores + bias
    const int erow = rowBase + wm * 64 + (lane >> 2);
    const int ecol = colBase + wn * 64 + (lane & 3) * 2;
    #pragma unroll
    for (int mi = 0; mi < 4; mi++) {
        #pragma unroll
        for (int ni = 0; ni < 8; ni++) {
            int r0 = erow + mi * 16;
            int c0 = ecol + ni * 8;
            float bx = bias[c0], by = bias[c0 + 1];
            float2 v0 = make_float2(acc[mi][ni][0] + bx, acc[mi][ni][1] + by);
            float2 v1 = make_float2(acc[mi][ni][2] + bx, acc[mi][ni][3] + by);
            *reinterpret_cast<float2*>(C + (size_t)r0 * N + c0)       = v0;
            *reinterpret_cast<float2*>(C + (size_t)(r0 + 8) * N + c0) = v1;
        }
    }
}

// ---------------------------------------------------------------------------
// Pass A: per-chunk U = (scale*K_c)^T @ V_c
// ---------------------------------------------------------------------------
__global__ __launch_bounds__(256)
void chunk_kv_kernel(const float* __restrict__ qkv, float* __restrict__ U)
{
    __shared__ float Ks[64][64];
    __shared__ float Vs[64][64];

    const int idx = blockIdx.x;
    const int c   = idx & (NCH - 1);
    const int bh  = idx >> 5;
    const int h   = bh & (HH - 1);
    const int b   = bh >> 4;

    const float* kb = qkv + ((size_t)(b * LL + c * 64)) * QKVN + DD + h * 64;
    const float* vb = kb + DD;
    const int tid = threadIdx.x;

    #pragma unroll
    for (int it = 0; it < 4; it++) {
        int e = tid + it * 256;
        int i = e >> 4;
        int c4 = (e & 15) << 2;
        float4 kv = *reinterpret_cast<const float4*>(kb + (size_t)i * QKVN + c4);
        Ks[i][c4 + 0] = kv.x * SCALE;
        Ks[i][c4 + 1] = kv.y * SCALE;
        Ks[i][c4 + 2] = kv.z * SCALE;
        Ks[i][c4 + 3] = kv.w * SCALE;
        float4 vv = *reinterpret_cast<const float4*>(vb + (size_t)i * QKVN + c4);
        *reinterpret_cast<float4*>(&Vs[i][c4]) = vv;
    }
    __syncthreads();

    const int tx = tid & 15;
    const int ty = tid >> 4;
    float acc[4][4] = {};
    #pragma unroll 8
    for (int i = 0; i < 64; i++) {
        float4 kp = *reinterpret_cast<const float4*>(&Ks[i][ty << 2]);
        float4 vq = *reinterpret_cast<const float4*>(&Vs[i][tx << 2]);
        float rk[4] = {kp.x, kp.y, kp.z, kp.w};
        float rv[4] = {vq.x, vq.y, vq.z, vq.w};
        #pragma unroll
        for (int p = 0; p < 4; p++)
            #pragma unroll
            for (int q = 0; q < 4; q++)
                acc[p][q] += rk[p] * rv[q];
    }

    float* ub = U + (size_t)idx * 4096;
    #pragma unroll
    for (int p = 0; p < 4; p++) {
        float4 o = make_float4(acc[p][0], acc[p][1], acc[p][2], acc[p][3]);
        *reinterpret_cast<float4*>(ub + (size_t)(((ty << 2) + p) * 64 + (tx << 2))) = o;
    }
}

// ---------------------------------------------------------------------------
// Pass B: exclusive chunk-prefix of 64x64 state per (b,h)
// ---------------------------------------------------------------------------
__global__ __launch_bounds__(256)
void scan_kernel(float* __restrict__ U)
{
    const int bh = blockIdx.x;
    const int tid = threadIdx.x;
    float* base = U + (size_t)bh * NCH * 4096;

    float4 run[4];
    #pragma unroll
    for (int g = 0; g < 4; g++) run[g] = make_float4(0.f, 0.f, 0.f, 0.f);

    for (int cix = 0; cix < NCH; cix++) {
        float4* p = reinterpret_cast<float4*>(base + (size_t)cix * 4096);
        #pragma unroll
        for (int g = 0; g < 4; g++) {
            float4 cur = p[tid + g * 256];
            p[tid + g * 256] = run[g];
            run[g].x += cur.x; run[g].y += cur.y;
            run[g].z += cur.z; run[g].w += cur.w;
        }
    }
}

// ---------------------------------------------------------------------------
// Pass C: Y_c = (Q_c (scale*K_c)^T ∘ tril) V_c + Q_c @ S_prefix
// Epilogue FUSED with the A-side bf16 split: writes y directly into a3
// as [hi | lo | hi] along K' for the output-projection GEMM.
// ---------------------------------------------------------------------------
__global__ __launch_bounds__(256)
void attn_out_kernel(const float* __restrict__ qkv, const float* __restrict__ S,
                     __nv_bfloat16* __restrict__ A3)
{
    extern __shared__ float sm[];
    float* QsT = sm;
    float* KsT = QsT + 64 * TP;
    float* AsT = KsT + 64 * TP;
    float* Vs  = AsT + 64 * TP;
    float* Ss  = Vs + 64 * 64;

    const int idx = blockIdx.x;
    const int c   = idx & (NCH - 1);
    const int bh  = idx >> 5;
    const int h   = bh & (HH - 1);
    const int b   = bh >> 4;

    const float* qb = qkv + ((size_t)(b * LL + c * 64)) * QKVN + h * 64;
    const float* kb = qb + DD;
    const float* vb = qb + 2 * DD;
    const float* sb = S + (size_t)idx * 4096;
    const int tid = threadIdx.x;

    {
        const int i = tid >> 2;
        #pragma unroll
        for (int it = 0; it < 4; it++) {
            int c4 = ((tid & 3) + it * 4) << 2;
            float4 q = *reinterpret_cast<const float4*>(qb + (size_t)i * QKVN + c4);
            QsT[(c4 + 0) * TP + i] = q.x;
            QsT[(c4 + 1) * TP + i] = q.y;
            QsT[(c4 + 2) * TP + i] = q.z;
            QsT[(c4 + 3) * TP + i] = q.w;
            float4 k = *reinterpret_cast<const float4*>(kb + (size_t)i * QKVN + c4);
            KsT[(c4 + 0) * TP + i] = k.x * SCALE;
            KsT[(c4 + 1) * TP + i] = k.y * SCALE;
            KsT[(c4 + 2) * TP + i] = k.z * SCALE;
            KsT[(c4 + 3) * TP + i] = k.w * SCALE;
        }
    }
    #pragma unroll
    for (int it = 0; it < 4; it++) {
        int e = tid + it * 256;
        int i = e >> 4;
        int c4 = (e & 15) << 2;
        float4 v = *reinterpret_cast<const float4*>(vb + (size_t)i * QKVN + c4);
        *reinterpret_cast<float4*>(&Vs[i * 64 + c4]) = v;
        float4 s = *reinterpret_cast<const float4*>(sb + (size_t)(i * 64 + c4));
        *reinterpret_cast<float4*>(&Ss[i * 64 + c4]) = s;
    }
    __syncthreads();

    const int tx = tid & 15;
    const int ty = tid >> 4;

    {
        float a[4][4] = {};
        #pragma unroll 4
        for (int p = 0; p < 64; p++) {
            float4 kj = *reinterpret_cast<const float4*>(&KsT[p * TP + (ty << 2)]);
            float4 qi = *reinterpret_cast<const float4*>(&QsT[p * TP + (tx << 2)]);
            float rk[4] = {kj.x, kj.y, kj.z, kj.w};
            float rq[4] = {qi.x, qi.y, qi.z, qi.w};
            #pragma unroll
            for (int jj = 0; jj < 4; jj++)
                #pragma unroll
                for (int ii = 0; ii < 4; ii++)
                    a[jj][ii] += rk[jj] * rq[ii];
        }
        #pragma unroll
        for (int jj = 0; jj < 4; jj++) {
            int j = (ty << 2) + jj;
            int i0 = tx << 2;
            float4 o;
            o.x = (j <= i0 + 0) ? a[jj][0] : 0.0f;
            o.y = (j <= i0 + 1) ? a[jj][1] : 0.0f;
            o.z = (j <= i0 + 2) ? a[jj][2] : 0.0f;
            o.w = (j <= i0 + 3) ? a[jj][3] : 0.0f;
            *reinterpret_cast<float4*>(&AsT[j * TP + i0]) = o;
        }
    }
    __syncthreads();

    {
        float acc[4][4] = {};
        #pragma unroll 4
        for (int j = 0; j < 64; j++) {
            float4 aj = *reinterpret_cast<const float4*>(&AsT[j * TP + (ty << 2)]);
            float4 vj = *reinterpret_cast<const float4*>(&Vs[j * 64 + (tx << 2)]);
            float ra[4] = {aj.x, aj.y, aj.z, aj.w};
            float rv[4] = {vj.x, vj.y, vj.z, vj.w};
            #pragma unroll
            for (int ii = 0; ii < 4; ii++)
                #pragma unroll
                for (int dd = 0; dd < 4; dd++)
                    acc[ii][dd] += ra[ii] * rv[dd];
        }
        #pragma unroll 4
        for (int p = 0; p < 64; p++) {
            float4 qp = *reinterpret_cast<const float4*>(&QsT[p * TP + (ty << 2)]);
            float4 sp = *reinterpret_cast<const float4*>(&Ss[p * 64 + (tx << 2)]);
            float rq[4] = {qp.x, qp.y, qp.z, qp.w};
            float rs[4] = {sp.x, sp.y, sp.z, sp.w};
            #pragma unroll
            for (int ii = 0; ii < 4; ii++)
                #pragma unroll
                for (int dd = 0; dd < 4; dd++)
                    acc[ii][dd] += rq[ii] * rs[dd];
        }

        // Fused A-side split epilogue: [hi | lo | hi] into a3 (K' layout)
        const int grow = b * LL + c * 64;           // global token row base
        const int col0 = h * 64 + (tx << 2);        // column within 0..1023
        #pragma unroll
        for (int ii = 0; ii < 4; ii++) {
            int r = grow + (ty << 2) + ii;
            __nv_bfloat16* ab = A3 + (size_t)r * KP + col0;
            __nv_bfloat162 hh0, hh1, ll0, ll1;
            float v0 = acc[ii][0], v1 = acc[ii][1], v2 = acc[ii][2], v3 = acc[ii][3];
            hh0.x = __float2bfloat16(v0);
            hh0.y = __float2bfloat16(v1);
            hh1.x = __float2bfloat16(v2);
            hh1.y = __float2bfloat16(v3);
            ll0.x = __float2bfloat16(v0 - __bfloat162float(hh0.x));
            ll0.y = __float2bfloat16(v1 - __bfloat162float(hh0.y));
            ll1.x = __float2bfloat16(v2 - __bfloat162float(hh1.x));
            ll1.y = __float2bfloat16(v3 - __bfloat162float(hh1.y));
            *reinterpret_cast<__nv_bfloat162*>(ab)            = hh0;
            *reinterpret_cast<__nv_bfloat162*>(ab + 2)        = hh1;
            *reinterpret_cast<__nv_bfloat162*>(ab + 1024)     = ll0;
            *reinterpret_cast<__nv_bfloat162*>(ab + 1026)     = ll1;
            *reinterpret_cast<__nv_bfloat162*>(ab + 2048)     = hh0;
            *reinterpret_cast<__nv_bfloat162*>(ab + 2050)     = hh1;
        }
    }
}

// ---------------------------------------------------------------------------
extern "C" void kernel_launch(void* const* d_in, const int* in_sizes, int n_in,
                              void* d_out, int out_size)
{
    const float* x      = (const float*)d_in[0];
    const float* Wqkv_w = (const float*)d_in[1];
    const float* Wqkv_b = (const float*)d_in[2];
    const float* out_w  = (const float*)d_in[3];
    const float* out_b  = (const float*)d_in[4];
    float* out = (float*)d_out;

    float *qkv, *u;
    __nv_bfloat16 *a3, *b3, *w23;
    cudaGetSymbolAddress((void**)&qkv, g_qkv);
    cudaGetSymbolAddress((void**)&u,   g_u);
    cudaGetSymbolAddress((void**)&a3,  g_a3);
    cudaGetSymbolAddress((void**)&b3,  g_b3);
    cudaGetSymbolAddress((void**)&w23, g_w23);

    const int smem_attn = (3 * 64 * TP + 2 * 64 * 64) * (int)sizeof(float);
    cudaFuncSetAttribute(attn_out_kernel,
                         cudaFuncAttributeMaxDynamicSharedMemorySize, smem_attn);
    cudaFuncSetAttribute(gemm_mma_nt,
                         cudaFuncAttributeMaxDynamicSharedMemorySize, GEMM_SMEM);

    // 1) split conversions for QKV GEMM
    split_convert<0><<<(MR * DD / 2 + 255) / 256, 256>>>(x, a3, MR * DD);
    split_convert<1><<<(QKVN * DD / 2 + 255) / 256, 256>>>(Wqkv_w, b3, QKVN * DD);

    // 2) QKV projection on tensor cores (HMMA)
    dim3 g1(QKVN / GBN, MR / GBM);  // 12 x 32
    gemm_mma_nt<<<g1, 256, GEMM_SMEM>>>(a3, b3, Wqkv_b, qkv, QKVN);

    // 3) chunked linear attention (fp32); attn_out writes bf16 split into a3
    chunk_kv_kernel<<<BB * HH * NCH, 256>>>(qkv, u);
    scan_kernel<<<BB * HH, 256>>>(u);
    attn_out_kernel<<<BB * HH * NCH, 256, smem_attn>>>(qkv, u, a3);

    // 4) split conversion for output-projection weights
    split_convert<1><<<(DD * DD / 2 + 255) / 256, 256>>>(out_w, w23, DD * DD);

    // 5) output projection on tensor cores (HMMA)
    dim3 g2(DD / GBN, MR / GBM);    // 4 x 32
    gemm_mma_nt<<<g2, 256, GEMM_SMEM>>>(a3, w23, out_b, out, DD);
}